// round 3
// baseline (speedup 1.0000x reference)
#include <cuda_runtime.h>

#define NN 8192
#define D 64
#define ALPHA 0.2f
#define CS 128   // scan chunk size
#define NC 64    // number of chunks (NN/CS)
#define TS 65    // smem tile stride: 65 % 32 == 1 -> conflict-free column access

// ---------------- device scratch (no allocation allowed) ----------------
__device__ float g_h[NN * D];
__device__ float g_f1[NN];
__device__ float g_f2[NN];
__device__ unsigned g_key[NN];
__device__ int   g_rank[NN];
__device__ int   g_perm[NN];
__device__ float g_f2s[NN];
__device__ float g_wlo[NN];            // exp(alpha * f2), sorted order
__device__ float g_whi[NN];            // exp(f2), sorted order
__device__ float g_LoP[(NN + 1) * D];  // chunk-local fwd prefix of wlo*h
__device__ float g_HiS[(NN + 1) * D];  // chunk-local bwd suffix of whi*h
__device__ float g_zLo[NN + 1];
__device__ float g_zHi[NN + 1];
__device__ float g_ofLo[D * NC];       // per (d, chunk): totals -> exclusive offsets
__device__ float g_ofHi[D * NC];
__device__ float g_ofzLo[NC];
__device__ float g_ofzHi[NC];

// ---------------- k1: h = x@Wt, f1/f2, 32-bit sort keys, zero ranks ----------------
__global__ void k1(const float* __restrict__ x, const float* __restrict__ Wt,
                   const float* __restrict__ a1, const float* __restrict__ b1,
                   const float* __restrict__ a2, const float* __restrict__ b2) {
    __shared__ float sW[D * D];
    __shared__ float sx[16][D];
    __shared__ float sh[16][D];
    int tid = threadIdx.x;        // 256
    int row0 = blockIdx.x * 16;
    for (int i = tid; i < D * D; i += 256) sW[i] = Wt[i];
    for (int i = tid; i < 16 * D; i += 256) sx[i >> 6][i & 63] = x[row0 * D + i];
    __syncthreads();
    int o = tid & 63, rg = tid >> 6;
    float a0 = 0.f, a1c = 0.f, a2c = 0.f, a3 = 0.f;
#pragma unroll
    for (int i = 0; i < D; i++) {
        float w = sW[i * D + o];
        a0  += sx[rg * 4 + 0][i] * w;
        a1c += sx[rg * 4 + 1][i] * w;
        a2c += sx[rg * 4 + 2][i] * w;
        a3  += sx[rg * 4 + 3][i] * w;
    }
    g_h[(row0 + rg * 4 + 0) * D + o] = a0;
    g_h[(row0 + rg * 4 + 1) * D + o] = a1c;
    g_h[(row0 + rg * 4 + 2) * D + o] = a2c;
    g_h[(row0 + rg * 4 + 3) * D + o] = a3;
    sh[rg * 4 + 0][o] = a0;
    sh[rg * 4 + 1][o] = a1c;
    sh[rg * 4 + 2][o] = a2c;
    sh[rg * 4 + 3][o] = a3;
    __syncthreads();
    int w = tid >> 5, lane = tid & 31;
#pragma unroll
    for (int q = 0; q < 2; q++) {
        int r = w * 2 + q;
        float h0 = sh[r][lane], h1 = sh[r][lane + 32];
        float s1 = h0 * a1[lane] + h1 * a1[lane + 32];
        float s2 = h0 * a2[lane] + h1 * a2[lane + 32];
#pragma unroll
        for (int off = 16; off; off >>= 1) {
            s1 += __shfl_down_sync(0xFFFFFFFFu, s1, off);
            s2 += __shfl_down_sync(0xFFFFFFFFu, s2, off);
        }
        if (lane == 0) {
            int row = row0 + r;
            float f1v = s1 + b1[0], f2v = s2 + b2[0];
            g_f1[row] = f1v;
            g_f2[row] = f2v;
            unsigned u = __float_as_uint(f2v);
            g_key[row] = (u >> 31) ? ~u : (u | 0x80000000u);  // order-preserving
            g_rank[row] = 0;
        }
    }
}

// ---------------- kRank: blocked counting rank sort (32-bit keys) ----------------
// grid 128: eb = i-chunk of 1024 (256 thr x 4), cb = j-chunk of 512 in smem.
// Ties resolved by index: j<i chunks use <=, j>i chunks use <, diagonal exact.
__global__ void kRank() {
    __shared__ unsigned sk[512];
    int tid = threadIdx.x;  // 256
    int eb = blockIdx.x & 7, cb = blockIdx.x >> 3;
    int i0 = eb * 1024;
    unsigned ki[4]; int ig[4]; int cnt[4] = {0, 0, 0, 0};
#pragma unroll
    for (int m = 0; m < 4; m++) { ig[m] = i0 + tid + 256 * m; ki[m] = g_key[ig[m]]; }
    sk[tid] = g_key[cb * 512 + tid];
    sk[tid + 256] = g_key[cb * 512 + 256 + tid];
    __syncthreads();
    if ((cb >> 1) == eb) {          // diagonal block
        int j0 = cb * 512;
        for (int j = 0; j < 512; j++) {
            unsigned kj = sk[j]; int jg = j0 + j;
#pragma unroll
            for (int m = 0; m < 4; m++)
                cnt[m] += (kj < ki[m]) || (kj == ki[m] && jg < ig[m]);
        }
    } else if (cb < eb * 2) {       // all j < i
#pragma unroll 4
        for (int j = 0; j < 512; j++) {
            unsigned kj = sk[j];
#pragma unroll
            for (int m = 0; m < 4; m++) cnt[m] += (kj <= ki[m]);
        }
    } else {                        // all j > i
#pragma unroll 4
        for (int j = 0; j < 512; j++) {
            unsigned kj = sk[j];
#pragma unroll
            for (int m = 0; m < 4; m++) cnt[m] += (kj < ki[m]);
        }
    }
#pragma unroll
    for (int m = 0; m < 4; m++) atomicAdd(&g_rank[ig[m]], cnt[m]);
}

// ---------------- kScatter: into sorted order + exp weights ----------------
__global__ void kScatter() {
    int i = blockIdx.x * 256 + threadIdx.x;
    int r = g_rank[i];
    float f = g_f2[i];
    g_perm[r] = i;
    g_f2s[r] = f;
    g_wlo[r] = expf(ALPHA * f);
    g_whi[r] = expf(f);
}

// ---------------- kScan: per-chunk warp-parallel scans (128 blocks) ----------------
// blockIdx: c = bx>>1, table = bx&1 (0 = Lo forward, 1 = Hi backward).
// Column 64 of the tile carries the weight itself (z scan).
__global__ void kScan() {
    extern __shared__ float s[];      // [CS][TS] = 33280 B
    __shared__ int   sperm[CS];
    __shared__ float sw[CS];
    int tid = threadIdx.x;            // 256
    int c = blockIdx.x >> 1, table = blockIdx.x & 1;
    int j0 = c * CS;
    if (tid < CS) {
        sperm[tid] = g_perm[j0 + tid];
        sw[tid] = table ? g_whi[j0 + tid] : g_wlo[j0 + tid];
    }
    __syncthreads();
    for (int idx = tid; idx < CS * D; idx += 256) {
        int j = idx >> 6, d = idx & 63;
        s[j * TS + d] = sw[j] * g_h[sperm[j] * D + d];
    }
    if (tid < CS) s[tid * TS + 64] = sw[tid];
    __syncthreads();
    int w = tid >> 5, lane = tid & 31;
    const unsigned F = 0xFFFFFFFFu;
    if (!table) {  // forward inclusive prefix per column, in place
        for (int d = w; d <= 64; d += 8) {
            float carry = 0.f;
#pragma unroll
            for (int m = 0; m < 4; m++) {
                int j = m * 32 + lane;
                float v = s[j * TS + d];
#pragma unroll
                for (int o = 1; o < 32; o <<= 1) { float t = __shfl_up_sync(F, v, o); if (lane >= o) v += t; }
                v += carry;
                carry = __shfl_sync(F, v, 31);
                s[j * TS + d] = v;
            }
            if (lane == 0) {
                if (d < 64) g_ofLo[d * NC + c] = carry; else g_ofzLo[c] = carry;
            }
        }
    } else {       // backward inclusive suffix per column, in place
        for (int d = w; d <= 64; d += 8) {
            float carry = 0.f;
#pragma unroll
            for (int m = 3; m >= 0; m--) {
                int j = m * 32 + lane;
                float v = s[j * TS + d];
#pragma unroll
                for (int o = 1; o < 32; o <<= 1) { float t = __shfl_down_sync(F, v, o); if (lane + o < 32) v += t; }
                v += carry;
                carry = __shfl_sync(F, v, 0);
                s[j * TS + d] = v;
            }
            if (lane == 0) {
                if (d < 64) g_ofHi[d * NC + c] = carry; else g_ofzHi[c] = carry;
            }
        }
    }
    __syncthreads();
    if (!table) {
        for (int idx = tid; idx < CS * D; idx += 256) {
            int j = idx >> 6, d = idx & 63;
            g_LoP[(j0 + j + 1) * D + d] = s[j * TS + d];
        }
        if (tid < CS) g_zLo[j0 + tid + 1] = s[tid * TS + 64];
        if (c == 0) {
            if (tid < D) g_LoP[tid] = 0.f;
            if (tid == D) g_zLo[0] = 0.f;
        }
    } else {
        for (int idx = tid; idx < CS * D; idx += 256) {
            int j = idx >> 6, d = idx & 63;
            g_HiS[(j0 + j) * D + d] = s[j * TS + d];
        }
        if (tid < CS) g_zHi[j0 + tid] = s[tid * TS + 64];
        if (c == NC - 1) {
            if (tid < D) g_HiS[NN * D + tid] = 0.f;
            if (tid == D) g_zHi[NN] = 0.f;
        }
    }
}

// ---------------- kS2: scan chunk totals -> exclusive offsets (in place) ----------------
__global__ void kS2() {
    int t = blockIdx.x * 4 + (threadIdx.x >> 5);
    int lane = threadIdx.x & 31;
    if (t >= 130) return;
    const unsigned F = 0xFFFFFFFFu;
    float* base;
    bool fwd;
    if (t < 64)        { base = g_ofLo + t * NC;        fwd = true;  }
    else if (t < 128)  { base = g_ofHi + (t - 64) * NC; fwd = false; }
    else if (t == 128) { base = g_ofzLo;                fwd = true;  }
    else               { base = g_ofzHi;                fwd = false; }
    float v0 = base[lane], v1 = base[lane + 32];
    if (fwd) {
        float x0 = v0;
#pragma unroll
        for (int o = 1; o < 32; o <<= 1) { float s = __shfl_up_sync(F, x0, o); if (lane >= o) x0 += s; }
        float tot0 = __shfl_sync(F, x0, 31);
        float x1 = v1;
#pragma unroll
        for (int o = 1; o < 32; o <<= 1) { float s = __shfl_up_sync(F, x1, o); if (lane >= o) x1 += s; }
        base[lane] = x0 - v0;
        base[lane + 32] = tot0 + x1 - v1;
    } else {
        float x1 = v1;
#pragma unroll
        for (int o = 1; o < 32; o <<= 1) { float s = __shfl_down_sync(F, x1, o); if (lane + o < 32) x1 += s; }
        float tot1 = __shfl_sync(F, x1, 0);
        float x0 = v0;
#pragma unroll
        for (int o = 1; o < 32; o <<= 1) { float s = __shfl_down_sync(F, x0, o); if (lane + o < 32) x0 += s; }
        base[lane] = x0 - v0 + tot1;
        base[lane + 32] = x1 - v1;
    }
}

// ---------------- kOut: per-row combine + ELU (32-ary cooperative search) ----------------
__global__ void kOut(float* __restrict__ out) {
    int w = threadIdx.x >> 5, lane = threadIdx.x & 31;
    int i = blockIdx.x * 8 + w;
    float f1 = g_f1[i];
    float thr = -f1;
    const unsigned F = 0xFFFFFFFFu;
    // k = #{j: f2s[j] <= thr} via 3-level 32-ary search
    unsigned m1 = __ballot_sync(F, g_f2s[lane * 256] <= thr);
    int c1 = __popc(m1);
    int k = 0;
    if (c1 > 0) {
        int base = (c1 - 1) * 256;
        unsigned m2 = __ballot_sync(F, g_f2s[base + lane * 8] <= thr);
        int c2 = __popc(m2);                 // >= 1 (probe at base is <= thr)
        int base2 = base + (c2 - 1) * 8;
        int idx3 = base2 + 1 + (lane & 7);
        unsigned m3 = __ballot_sync(F, (idx3 < NN) ? (g_f2s[idx3] <= thr) : false);
        k = base2 + 1 + __popc(m3 & 0xFFu);
    } else {
        __ballot_sync(F, false);             // keep ballot count uniform
        __ballot_sync(F, false);
    }
    int ckLo = (k == 0) ? 0 : ((k - 1) >> 7);
    int ckHi = k >> 7;
    bool hasHi = (k < NN);
    float e1 = expf(f1), ea = expf(ALPHA * f1);
    float zLoV = g_zLo[k] + g_ofzLo[ckLo];
    float zHiV = hasHi ? (g_zHi[k] + g_ofzHi[ckHi]) : 0.f;
    float inv = 1.0f / (e1 * zHiV + ea * zLoV);
#pragma unroll
    for (int p = 0; p < 2; p++) {
        int d = lane + 32 * p;
        float lo = g_LoP[k * D + d] + g_ofLo[d * NC + ckLo];
        float hi = hasHi ? (g_HiS[k * D + d] + g_ofHi[d * NC + ckHi]) : 0.f;
        float r = (e1 * hi + ea * lo) * inv;
        out[i * D + d] = (r > 0.f) ? r : (expf(r) - 1.f);
    }
}

extern "C" void kernel_launch(void* const* d_in, const int* in_sizes, int n_in,
                              void* d_out, int out_size) {
    const float* x  = (const float*)d_in[0];
    const float* Wt = (const float*)d_in[1];
    const float* a1 = (const float*)d_in[2];
    const float* b1 = (const float*)d_in[3];
    const float* a2 = (const float*)d_in[4];
    const float* b2 = (const float*)d_in[5];
    float* out = (float*)d_out;

    k1<<<NN / 16, 256>>>(x, Wt, a1, b1, a2, b2);
    kRank<<<128, 256>>>();
    kScatter<<<32, 256>>>();
    kScan<<<NC * 2, 256, CS * TS * 4>>>();
    kS2<<<33, 128>>>();
    kOut<<<NN / 8, 256>>>(out);
}

// round 4
// speedup vs baseline: 2.2785x; 2.2785x over previous
#include <cuda_runtime.h>

#define NN 8192
#define D 64
#define ALPHA 0.2f
#define CS 32          // scan chunk size (one warp-scan, no carry chain)
#define NC 256         // number of chunks (NN/CS)
#define TS 65          // tile stride: conflict-free columns

// ---------------- device scratch (no allocation allowed) ----------------
__device__ float g_h[NN * D];
__device__ float g_f1[NN];
__device__ float g_f2[NN];
__device__ unsigned long long g_key[NN];
__device__ int   g_rank[NN];
__device__ int   g_perm[NN];
__device__ float g_f2s[NN];
__device__ float g_wlo[NN];            // exp(alpha * f2), sorted order
__device__ float g_whi[NN];            // exp(f2), sorted order
__device__ float g_LoP[(NN + 1) * D];  // chunk-local fwd prefix of wlo*h
__device__ float g_HiS[(NN + 1) * D];  // chunk-local bwd suffix of whi*h
__device__ float g_zLo[NN + 1];
__device__ float g_zHi[NN + 1];
__device__ float g_ofLo[D * NC];       // per (d, chunk): totals -> exclusive offsets
__device__ float g_ofHi[D * NC];
__device__ float g_ofzLo[NC];
__device__ float g_ofzHi[NC];

// ---------------- k1: h = x@Wt, f1/f2, u64 sort keys, zero ranks ----------------
__global__ void k1(const float* __restrict__ x, const float* __restrict__ Wt,
                   const float* __restrict__ a1, const float* __restrict__ b1,
                   const float* __restrict__ a2, const float* __restrict__ b2) {
    __shared__ float sW[D * D];
    __shared__ float sx[16][D];
    __shared__ float sh[16][D];
    int tid = threadIdx.x;        // 256
    int row0 = blockIdx.x * 16;
    for (int i = tid; i < D * D; i += 256) sW[i] = Wt[i];
    for (int i = tid; i < 16 * D; i += 256) sx[i >> 6][i & 63] = x[row0 * D + i];
    __syncthreads();
    int o = tid & 63, rg = tid >> 6;
    float a0 = 0.f, a1c = 0.f, a2c = 0.f, a3 = 0.f;
#pragma unroll
    for (int i = 0; i < D; i++) {
        float w = sW[i * D + o];
        a0  += sx[rg * 4 + 0][i] * w;
        a1c += sx[rg * 4 + 1][i] * w;
        a2c += sx[rg * 4 + 2][i] * w;
        a3  += sx[rg * 4 + 3][i] * w;
    }
    g_h[(row0 + rg * 4 + 0) * D + o] = a0;
    g_h[(row0 + rg * 4 + 1) * D + o] = a1c;
    g_h[(row0 + rg * 4 + 2) * D + o] = a2c;
    g_h[(row0 + rg * 4 + 3) * D + o] = a3;
    sh[rg * 4 + 0][o] = a0;
    sh[rg * 4 + 1][o] = a1c;
    sh[rg * 4 + 2][o] = a2c;
    sh[rg * 4 + 3][o] = a3;
    __syncthreads();
    int w = tid >> 5, lane = tid & 31;
#pragma unroll
    for (int q = 0; q < 2; q++) {
        int r = w * 2 + q;
        float h0 = sh[r][lane], h1 = sh[r][lane + 32];
        float s1 = h0 * a1[lane] + h1 * a1[lane + 32];
        float s2 = h0 * a2[lane] + h1 * a2[lane + 32];
#pragma unroll
        for (int off = 16; off; off >>= 1) {
            s1 += __shfl_down_sync(0xFFFFFFFFu, s1, off);
            s2 += __shfl_down_sync(0xFFFFFFFFu, s2, off);
        }
        if (lane == 0) {
            int row = row0 + r;
            float f1v = s1 + b1[0], f2v = s2 + b2[0];
            g_f1[row] = f1v;
            g_f2[row] = f2v;
            unsigned u = __float_as_uint(f2v);
            u = (u >> 31) ? ~u : (u | 0x80000000u);   // order-preserving map
            g_key[row] = ((unsigned long long)u << 13) | (unsigned)row;  // tie-break
            g_rank[row] = 0;
        }
    }
}

// ---------------- kRank: counting rank sort (round-2 proven version) ----------------
// 512 blocks: (element-block eb of 128) x (comparison-chunk cb of 1024)
__global__ void kRank() {
    __shared__ unsigned long long sk[1024];
    int tid = threadIdx.x;  // 128
    int eb = blockIdx.x >> 3, cb = blockIdx.x & 7;
    int i = eb * 128 + tid;
    unsigned long long ki = g_key[i];
#pragma unroll
    for (int m = 0; m < 8; m++) sk[tid + m * 128] = g_key[cb * 1024 + tid + m * 128];
    __syncthreads();
    int cnt = 0;
#pragma unroll 8
    for (int j = 0; j < 1024; j++) cnt += (sk[j] < ki);
    atomicAdd(&g_rank[i], cnt);
}

// ---------------- kScatter: into sorted order + exp weights ----------------
__global__ void kScatter() {
    int i = blockIdx.x * 256 + threadIdx.x;
    int r = g_rank[i];
    float f = g_f2[i];
    g_perm[r] = i;
    g_f2s[r] = f;
    g_wlo[r] = expf(ALPHA * f);
    g_whi[r] = expf(f);
}

// ---------------- kScan: 512 blocks, CS=32, single-round warp scans ----------------
// bx: c = bx>>1 (chunk), table = bx&1 (0 = Lo fwd, 1 = Hi bwd).
// Tile column 64 carries the weight itself (z scan).
__global__ void kScan() {
    __shared__ float s[CS * TS];          // 8320 B
    __shared__ int   sperm[CS];
    __shared__ float sw[CS];
    int tid = threadIdx.x;                // 128
    int c = blockIdx.x >> 1, table = blockIdx.x & 1;
    int j0 = c * CS;
    if (tid < CS) {
        sperm[tid] = g_perm[j0 + tid];
        sw[tid] = table ? g_whi[j0 + tid] : g_wlo[j0 + tid];
    }
    __syncthreads();
#pragma unroll
    for (int it = 0; it < 16; it++) {
        int idx = it * 128 + tid;
        int j = idx >> 6, d = idx & 63;
        s[j * TS + d] = sw[j] * g_h[sperm[j] * D + d];
    }
    if (tid < CS) s[tid * TS + 64] = sw[tid];
    __syncthreads();
    int w = tid >> 5, lane = tid & 31;
    const unsigned F = 0xFFFFFFFFu;
    if (!table) {  // forward inclusive prefix per column (single 32-scan)
        for (int d = w; d <= 64; d += 4) {
            float v = s[lane * TS + d];
#pragma unroll
            for (int o = 1; o < 32; o <<= 1) { float t = __shfl_up_sync(F, v, o); if (lane >= o) v += t; }
            s[lane * TS + d] = v;
            if (lane == 31) {
                if (d < 64) g_ofLo[d * NC + c] = v; else g_ofzLo[c] = v;
            }
        }
    } else {       // backward inclusive suffix per column
        for (int d = w; d <= 64; d += 4) {
            float v = s[lane * TS + d];
#pragma unroll
            for (int o = 1; o < 32; o <<= 1) { float t = __shfl_down_sync(F, v, o); if (lane + o < 32) v += t; }
            s[lane * TS + d] = v;
            if (lane == 0) {
                if (d < 64) g_ofHi[d * NC + c] = v; else g_ofzHi[c] = v;
            }
        }
    }
    __syncthreads();
    if (!table) {
#pragma unroll
        for (int it = 0; it < 16; it++) {
            int idx = it * 128 + tid;
            int j = idx >> 6, d = idx & 63;
            g_LoP[(j0 + j + 1) * D + d] = s[j * TS + d];
        }
        if (tid < CS) g_zLo[j0 + tid + 1] = s[tid * TS + 64];
        if (c == 0) {
            if (tid < D) g_LoP[tid] = 0.f;
            if (tid == D) g_zLo[0] = 0.f;
        }
    } else {
#pragma unroll
        for (int it = 0; it < 16; it++) {
            int idx = it * 128 + tid;
            int j = idx >> 6, d = idx & 63;
            g_HiS[(j0 + j) * D + d] = s[j * TS + d];
        }
        if (tid < CS) g_zHi[j0 + tid] = s[tid * TS + 64];
        if (c == NC - 1) {
            if (tid < D) g_HiS[NN * D + tid] = 0.f;
            if (tid == D) g_zHi[NN] = 0.f;
        }
    }
}

// ---------------- kS2: scan 256 chunk totals per column -> exclusive offsets ----------------
__global__ void kS2() {
    int t = blockIdx.x * 4 + (threadIdx.x >> 5);
    int lane = threadIdx.x & 31;
    if (t >= 130) return;
    const unsigned F = 0xFFFFFFFFu;
    float* base;
    bool fwd;
    if (t < 64)        { base = g_ofLo + t * NC;        fwd = true;  }
    else if (t < 128)  { base = g_ofHi + (t - 64) * NC; fwd = false; }
    else if (t == 128) { base = g_ofzLo;                fwd = true;  }
    else               { base = g_ofzHi;                fwd = false; }
    float carry = 0.f;
    if (fwd) {
#pragma unroll
        for (int m = 0; m < 8; m++) {
            float v = base[m * 32 + lane];
            float x = v;
#pragma unroll
            for (int o = 1; o < 32; o <<= 1) { float s = __shfl_up_sync(F, x, o); if (lane >= o) x += s; }
            float incl = x + carry;
            base[m * 32 + lane] = incl - v;        // exclusive prefix
            carry = __shfl_sync(F, incl, 31);
        }
    } else {
#pragma unroll
        for (int m = 7; m >= 0; m--) {
            float v = base[m * 32 + lane];
            float x = v;
#pragma unroll
            for (int o = 1; o < 32; o <<= 1) { float s = __shfl_down_sync(F, x, o); if (lane + o < 32) x += s; }
            float incl = x + carry;
            base[m * 32 + lane] = incl - v;        // exclusive suffix
            carry = __shfl_sync(F, incl, 0);
        }
    }
}

// ---------------- kOut: per-row combine + ELU (round-2 proven search) ----------------
__global__ void kOut(float* __restrict__ out) {
    int w = threadIdx.x >> 5, lane = threadIdx.x & 31;
    int i = blockIdx.x * 8 + w;
    float f1 = g_f1[i];
    float thr = -f1;
    int k = 0;
    if (lane == 0) {
        int lo = 0, hi = NN;
        while (lo < hi) { int m = (lo + hi) >> 1; if (g_f2s[m] <= thr) lo = m + 1; else hi = m; }
        k = lo;
    }
    k = __shfl_sync(0xFFFFFFFFu, k, 0);
    int ckLo = (k == 0) ? 0 : ((k - 1) >> 5);
    int ckHi = k >> 5;
    bool hasHi = (k < NN);
    float e1 = expf(f1), ea = expf(ALPHA * f1);
    float zLoV = g_zLo[k] + g_ofzLo[ckLo];
    float zHiV = hasHi ? (g_zHi[k] + g_ofzHi[ckHi]) : 0.f;
    float inv = 1.0f / (e1 * zHiV + ea * zLoV);
#pragma unroll
    for (int p = 0; p < 2; p++) {
        int d = lane + 32 * p;
        float lo = g_LoP[k * D + d] + g_ofLo[d * NC + ckLo];
        float hi = hasHi ? (g_HiS[k * D + d] + g_ofHi[d * NC + ckHi]) : 0.f;
        float r = (e1 * hi + ea * lo) * inv;
        out[i * D + d] = (r > 0.f) ? r : (expf(r) - 1.f);
    }
}

extern "C" void kernel_launch(void* const* d_in, const int* in_sizes, int n_in,
                              void* d_out, int out_size) {
    const float* x  = (const float*)d_in[0];
    const float* Wt = (const float*)d_in[1];
    const float* a1 = (const float*)d_in[2];
    const float* b1 = (const float*)d_in[3];
    const float* a2 = (const float*)d_in[4];
    const float* b2 = (const float*)d_in[5];
    float* out = (float*)d_out;

    k1<<<NN / 16, 256>>>(x, Wt, a1, b1, a2, b2);
    kRank<<<512, 128>>>();
    kScatter<<<32, 256>>>();
    kScan<<<NC * 2, 128>>>();
    kS2<<<33, 128>>>();
    kOut<<<NN / 8, 256>>>(out);
}

// round 5
// speedup vs baseline: 2.5985x; 1.1404x over previous
#include <cuda_runtime.h>

#define NN 8192
#define D 64
#define ALPHA 0.2f
#define CS 32          // scan chunk size (one warp-scan, no carry chain)
#define NC 256         // number of chunks (NN/CS)
#define HTS 33         // half-tile stride: 33 % 32 == 1 -> conflict-free columns

// ---------------- device scratch (no allocation allowed) ----------------
__device__ float g_h[NN * D];
__device__ float g_f1[NN];
__device__ float g_f2[NN];
__device__ unsigned long long g_key[NN];
__device__ int   g_rank[NN];
__device__ int   g_perm[NN];
__device__ float g_f2s[NN];
__device__ float g_wlo[NN];            // exp(alpha * f2), sorted order
__device__ float g_whi[NN];            // exp(f2), sorted order
__device__ float g_LoP[(NN + 1) * D];  // chunk-local fwd prefix of wlo*h
__device__ float g_HiS[(NN + 1) * D];  // chunk-local bwd suffix of whi*h
__device__ float g_zLo[NN + 1];
__device__ float g_zHi[NN + 1];
__device__ float g_ofLo[D * NC];       // per (d, chunk): totals -> exclusive offsets
__device__ float g_ofHi[D * NC];
__device__ float g_ofzLo[NC];
__device__ float g_ofzHi[NC];

// ---------------- k1: h = x@Wt, f1/f2, u64 sort keys, zero ranks ----------------
__global__ void k1(const float* __restrict__ x, const float* __restrict__ Wt,
                   const float* __restrict__ a1, const float* __restrict__ b1,
                   const float* __restrict__ a2, const float* __restrict__ b2) {
    __shared__ float sW[D * D];
    __shared__ float sx[16][D];
    __shared__ float sh[16][D];
    int tid = threadIdx.x;        // 256
    int row0 = blockIdx.x * 16;
    for (int i = tid; i < D * D; i += 256) sW[i] = Wt[i];
    for (int i = tid; i < 16 * D; i += 256) sx[i >> 6][i & 63] = x[row0 * D + i];
    __syncthreads();
    int o = tid & 63, rg = tid >> 6;
    float a0 = 0.f, a1c = 0.f, a2c = 0.f, a3 = 0.f;
#pragma unroll
    for (int i = 0; i < D; i++) {
        float w = sW[i * D + o];
        a0  += sx[rg * 4 + 0][i] * w;
        a1c += sx[rg * 4 + 1][i] * w;
        a2c += sx[rg * 4 + 2][i] * w;
        a3  += sx[rg * 4 + 3][i] * w;
    }
    g_h[(row0 + rg * 4 + 0) * D + o] = a0;
    g_h[(row0 + rg * 4 + 1) * D + o] = a1c;
    g_h[(row0 + rg * 4 + 2) * D + o] = a2c;
    g_h[(row0 + rg * 4 + 3) * D + o] = a3;
    sh[rg * 4 + 0][o] = a0;
    sh[rg * 4 + 1][o] = a1c;
    sh[rg * 4 + 2][o] = a2c;
    sh[rg * 4 + 3][o] = a3;
    __syncthreads();
    int w = tid >> 5, lane = tid & 31;
#pragma unroll
    for (int q = 0; q < 2; q++) {
        int r = w * 2 + q;
        float h0 = sh[r][lane], h1 = sh[r][lane + 32];
        float s1 = h0 * a1[lane] + h1 * a1[lane + 32];
        float s2 = h0 * a2[lane] + h1 * a2[lane + 32];
#pragma unroll
        for (int off = 16; off; off >>= 1) {
            s1 += __shfl_down_sync(0xFFFFFFFFu, s1, off);
            s2 += __shfl_down_sync(0xFFFFFFFFu, s2, off);
        }
        if (lane == 0) {
            int row = row0 + r;
            float f1v = s1 + b1[0], f2v = s2 + b2[0];
            g_f1[row] = f1v;
            g_f2[row] = f2v;
            unsigned u = __float_as_uint(f2v);
            u = (u >> 31) ? ~u : (u | 0x80000000u);   // order-preserving map
            g_key[row] = ((unsigned long long)u << 13) | (unsigned)row;  // tie-break
            g_rank[row] = 0;
        }
    }
}

// ---------------- kRank: counting rank sort, 1024 blocks ----------------
// eb = element-chunk of 128 (64 of them), cb = comparison-chunk of 512 (16 of them)
__global__ void kRank() {
    __shared__ unsigned long long sk[512];
    int tid = threadIdx.x;  // 128
    int eb = blockIdx.x >> 4, cb = blockIdx.x & 15;
    int i = eb * 128 + tid;
    unsigned long long ki = g_key[i];
#pragma unroll
    for (int m = 0; m < 4; m++) sk[tid + m * 128] = g_key[cb * 512 + tid + m * 128];
    __syncthreads();
    int cnt = 0;
#pragma unroll 8
    for (int j = 0; j < 512; j++) cnt += (sk[j] < ki);
    atomicAdd(&g_rank[i], cnt);
}

// ---------------- kScatter: into sorted order + exp weights ----------------
__global__ void kScatter() {
    int i = blockIdx.x * 256 + threadIdx.x;
    int r = g_rank[i];
    float f = g_f2[i];
    g_perm[r] = i;
    g_f2s[r] = f;
    g_wlo[r] = expf(ALPHA * f);
    g_whi[r] = expf(f);
}

// ---------------- kScan: 1024 blocks (chunk x table x d-half) ----------------
// bx: c = bx>>2, table = (bx>>1)&1 (0 = Lo fwd, 1 = Hi bwd), half = bx&1.
// half 0 covers d 0..31 plus the z column; half 1 covers d 32..63.
__global__ void kScan() {
    __shared__ float s[CS * HTS];         // 4224 B
    __shared__ int   sperm[CS];
    __shared__ float sw[CS];
    int tid = threadIdx.x;                // 128
    int c = blockIdx.x >> 2, table = (blockIdx.x >> 1) & 1, half = blockIdx.x & 1;
    int j0 = c * CS;
    int d0 = half * 32;
    if (tid < CS) {
        sperm[tid] = g_perm[j0 + tid];
        sw[tid] = table ? g_whi[j0 + tid] : g_wlo[j0 + tid];
    }
    __syncthreads();
    int w = tid >> 5, lane = tid & 31;
#pragma unroll
    for (int it = 0; it < 8; it++) {
        int j = it * 4 + w;
        s[j * HTS + lane] = sw[j] * g_h[sperm[j] * D + d0 + lane];
    }
    if (half == 0 && tid < CS) s[tid * HTS + 32] = sw[tid];
    __syncthreads();
    const unsigned F = 0xFFFFFFFFu;
    int ncols = (half == 0) ? 33 : 32;   // col 32 of half 0 = z column
    if (!table) {  // forward inclusive prefix per column (single 32-scan)
        for (int dd = w; dd < ncols; dd += 4) {
            float v = s[lane * HTS + dd];
#pragma unroll
            for (int o = 1; o < 32; o <<= 1) { float t = __shfl_up_sync(F, v, o); if (lane >= o) v += t; }
            s[lane * HTS + dd] = v;
            if (lane == 31) {
                if (dd < 32) g_ofLo[(d0 + dd) * NC + c] = v; else g_ofzLo[c] = v;
            }
        }
    } else {       // backward inclusive suffix per column
        for (int dd = w; dd < ncols; dd += 4) {
            float v = s[lane * HTS + dd];
#pragma unroll
            for (int o = 1; o < 32; o <<= 1) { float t = __shfl_down_sync(F, v, o); if (lane + o < 32) v += t; }
            s[lane * HTS + dd] = v;
            if (lane == 0) {
                if (dd < 32) g_ofHi[(d0 + dd) * NC + c] = v; else g_ofzHi[c] = v;
            }
        }
    }
    __syncthreads();
    if (!table) {
#pragma unroll
        for (int it = 0; it < 8; it++) {
            int j = it * 4 + w;
            g_LoP[(j0 + j + 1) * D + d0 + lane] = s[j * HTS + lane];
        }
        if (half == 0 && tid < CS) g_zLo[j0 + tid + 1] = s[tid * HTS + 32];
        if (c == 0) {
            if (tid < 32) g_LoP[d0 + tid] = 0.f;
            if (half == 0 && tid == 32) g_zLo[0] = 0.f;
        }
    } else {
#pragma unroll
        for (int it = 0; it < 8; it++) {
            int j = it * 4 + w;
            g_HiS[(j0 + j) * D + d0 + lane] = s[j * HTS + lane];
        }
        if (half == 0 && tid < CS) g_zHi[j0 + tid] = s[tid * HTS + 32];
        if (c == NC - 1) {
            if (tid < 32) g_HiS[NN * D + d0 + tid] = 0.f;
            if (half == 0 && tid == 32) g_zHi[NN] = 0.f;
        }
    }
}

// ---------------- kS2: scan 256 chunk totals per column -> exclusive offsets ----------------
__global__ void kS2() {
    int t = blockIdx.x * 4 + (threadIdx.x >> 5);
    int lane = threadIdx.x & 31;
    if (t >= 130) return;
    const unsigned F = 0xFFFFFFFFu;
    float* base;
    bool fwd;
    if (t < 64)        { base = g_ofLo + t * NC;        fwd = true;  }
    else if (t < 128)  { base = g_ofHi + (t - 64) * NC; fwd = false; }
    else if (t == 128) { base = g_ofzLo;                fwd = true;  }
    else               { base = g_ofzHi;                fwd = false; }
    float carry = 0.f;
    if (fwd) {
#pragma unroll
        for (int m = 0; m < 8; m++) {
            float v = base[m * 32 + lane];
            float x = v;
#pragma unroll
            for (int o = 1; o < 32; o <<= 1) { float s = __shfl_up_sync(F, x, o); if (lane >= o) x += s; }
            float incl = x + carry;
            base[m * 32 + lane] = incl - v;        // exclusive prefix
            carry = __shfl_sync(F, incl, 31);
        }
    } else {
#pragma unroll
        for (int m = 7; m >= 0; m--) {
            float v = base[m * 32 + lane];
            float x = v;
#pragma unroll
            for (int o = 1; o < 32; o <<= 1) { float s = __shfl_down_sync(F, x, o); if (lane + o < 32) x += s; }
            float incl = x + carry;
            base[m * 32 + lane] = incl - v;        // exclusive suffix
            carry = __shfl_sync(F, incl, 0);
        }
    }
}

// ---------------- kOut: per-row combine + ELU (smem-staged search) ----------------
__global__ void kOut(float* __restrict__ out) {
    __shared__ float sf[256];             // f2s samples at stride 32
    int tid = threadIdx.x;                // 256
    sf[tid] = g_f2s[tid * 32];
    __syncthreads();
    int w = tid >> 5, lane = tid & 31;
    int i = blockIdx.x * 8 + w;
    float f1 = g_f1[i];
    float thr = -f1;
    const unsigned F = 0xFFFFFFFFu;
    // window: lo = # samples <= thr (all lanes compute identically, LDS broadcast)
    int lo = 0, hi = 256;
#pragma unroll
    for (int it = 0; it < 8; it++) { int m = (lo + hi) >> 1; lo = (sf[m] <= thr) ? m + 1 : lo; hi = (sf[m] <= thr) ? hi : m; }
    int k;
    if (lo == 0) {
        __ballot_sync(F, false);
        k = 0;
    } else {
        int win = lo - 1;                 // f2s[win*32] <= thr; k in [win*32+1, win*32+32]
        int idx = win * 32 + 1 + lane;
        unsigned m = __ballot_sync(F, (idx < NN) ? (g_f2s[idx] <= thr) : false);
        k = win * 32 + 1 + __popc(m);
    }
    int ckLo = (k == 0) ? 0 : ((k - 1) >> 5);
    int ckHi = k >> 5;
    bool hasHi = (k < NN);
    float e1 = expf(f1), ea = expf(ALPHA * f1);
    float zLoV = g_zLo[k] + g_ofzLo[ckLo];
    float zHiV = hasHi ? (g_zHi[k] + g_ofzHi[ckHi]) : 0.f;
    float inv = 1.0f / (e1 * zHiV + ea * zLoV);
#pragma unroll
    for (int p = 0; p < 2; p++) {
        int d = lane + 32 * p;
        float lov = g_LoP[k * D + d] + g_ofLo[d * NC + ckLo];
        float hiv = hasHi ? (g_HiS[k * D + d] + g_ofHi[d * NC + ckHi]) : 0.f;
        float r = (e1 * hiv + ea * lov) * inv;
        out[i * D + d] = (r > 0.f) ? r : (expf(r) - 1.f);
    }
}

extern "C" void kernel_launch(void* const* d_in, const int* in_sizes, int n_in,
                              void* d_out, int out_size) {
    const float* x  = (const float*)d_in[0];
    const float* Wt = (const float*)d_in[1];
    const float* a1 = (const float*)d_in[2];
    const float* b1 = (const float*)d_in[3];
    const float* a2 = (const float*)d_in[4];
    const float* b2 = (const float*)d_in[5];
    float* out = (float*)d_out;

    k1<<<NN / 16, 256>>>(x, Wt, a1, b1, a2, b2);
    kRank<<<1024, 128>>>();
    kScatter<<<32, 256>>>();
    kScan<<<NC * 4, 128>>>();
    kS2<<<33, 128>>>();
    kOut<<<NN / 8, 256>>>(out);
}

// round 6
// speedup vs baseline: 2.6004x; 1.0007x over previous
#include <cuda_runtime.h>

#define NN 8192
#define D 64
#define ALPHA 0.2f
#define CS 32          // scan chunk size (one warp-scan, no carry chain)
#define NC 256         // number of chunks (NN/CS)
#define HTS 33         // half-tile stride: 33 % 32 == 1 -> conflict-free columns

// ---------------- device scratch (no allocation allowed) ----------------
__device__ float g_h[NN * D];
__device__ float g_f1[NN];
__device__ float g_f2[NN];
__device__ unsigned long long g_key[NN];
__device__ int   g_rank[NN];
__device__ int   g_perm[NN];
__device__ float g_f2s[NN];
__device__ float g_wlo[NN];            // exp(alpha * f2), sorted order
__device__ float g_whi[NN];            // exp(f2), sorted order
__device__ float g_LoP[(NN + 1) * D];  // chunk-local fwd prefix of wlo*h
__device__ float g_HiS[(NN + 1) * D];  // chunk-local bwd suffix of whi*h
__device__ float g_zLo[NN + 1];
__device__ float g_zHi[NN + 1];
__device__ float g_ofLo[D * NC];       // per (d, chunk): totals -> exclusive offsets
__device__ float g_ofHi[D * NC];
__device__ float g_ofzLo[NC];
__device__ float g_ofzHi[NC];

// ---------------- k1: h = x@Wt, f1/f2, u64 sort keys, zero ranks ----------------
__global__ void k1(const float* __restrict__ x, const float* __restrict__ Wt,
                   const float* __restrict__ a1, const float* __restrict__ b1,
                   const float* __restrict__ a2, const float* __restrict__ b2) {
    __shared__ float sW[D * D];
    __shared__ float sx[16][D];
    __shared__ float sh[16][D];
    int tid = threadIdx.x;        // 256
    int row0 = blockIdx.x * 16;
    for (int i = tid; i < D * D; i += 256) sW[i] = Wt[i];
    for (int i = tid; i < 16 * D; i += 256) sx[i >> 6][i & 63] = x[row0 * D + i];
    __syncthreads();
    int o = tid & 63, rg = tid >> 6;
    float a0 = 0.f, a1c = 0.f, a2c = 0.f, a3 = 0.f;
#pragma unroll
    for (int i = 0; i < D; i++) {
        float w = sW[i * D + o];
        a0  += sx[rg * 4 + 0][i] * w;
        a1c += sx[rg * 4 + 1][i] * w;
        a2c += sx[rg * 4 + 2][i] * w;
        a3  += sx[rg * 4 + 3][i] * w;
    }
    g_h[(row0 + rg * 4 + 0) * D + o] = a0;
    g_h[(row0 + rg * 4 + 1) * D + o] = a1c;
    g_h[(row0 + rg * 4 + 2) * D + o] = a2c;
    g_h[(row0 + rg * 4 + 3) * D + o] = a3;
    sh[rg * 4 + 0][o] = a0;
    sh[rg * 4 + 1][o] = a1c;
    sh[rg * 4 + 2][o] = a2c;
    sh[rg * 4 + 3][o] = a3;
    __syncthreads();
    int w = tid >> 5, lane = tid & 31;
#pragma unroll
    for (int q = 0; q < 2; q++) {
        int r = w * 2 + q;
        float h0 = sh[r][lane], h1 = sh[r][lane + 32];
        float s1 = h0 * a1[lane] + h1 * a1[lane + 32];
        float s2 = h0 * a2[lane] + h1 * a2[lane + 32];
#pragma unroll
        for (int off = 16; off; off >>= 1) {
            s1 += __shfl_down_sync(0xFFFFFFFFu, s1, off);
            s2 += __shfl_down_sync(0xFFFFFFFFu, s2, off);
        }
        if (lane == 0) {
            int row = row0 + r;
            float f1v = s1 + b1[0], f2v = s2 + b2[0];
            g_f1[row] = f1v;
            g_f2[row] = f2v;
            unsigned u = __float_as_uint(f2v);
            u = (u >> 31) ? ~u : (u | 0x80000000u);   // order-preserving map
            g_key[row] = ((unsigned long long)u << 13) | (unsigned)row;  // tie-break
            g_rank[row] = 0;
        }
    }
}

// ---------------- kRank: counting rank sort, 1024 blocks ----------------
// eb = element-chunk of 128 (64 of them), cb = comparison-chunk of 512 (16 of them)
__global__ void kRank() {
    __shared__ unsigned long long sk[512];
    int tid = threadIdx.x;  // 128
    int eb = blockIdx.x >> 4, cb = blockIdx.x & 15;
    int i = eb * 128 + tid;
    unsigned long long ki = g_key[i];
#pragma unroll
    for (int m = 0; m < 4; m++) sk[tid + m * 128] = g_key[cb * 512 + tid + m * 128];
    __syncthreads();
    int cnt = 0;
#pragma unroll 8
    for (int j = 0; j < 512; j++) cnt += (sk[j] < ki);
    atomicAdd(&g_rank[i], cnt);
}

// ---------------- kScatter: into sorted order + exp weights ----------------
__global__ void kScatter() {
    int i = blockIdx.x * 256 + threadIdx.x;
    int r = g_rank[i];
    float f = g_f2[i];
    g_perm[r] = i;
    g_f2s[r] = f;
    g_wlo[r] = expf(ALPHA * f);
    g_whi[r] = expf(f);
}

// ---------------- kScan: 1024 blocks (chunk x table x d-half) ----------------
// bx: c = bx>>2, table = (bx>>1)&1 (0 = Lo fwd, 1 = Hi bwd), half = bx&1.
// half 0 covers d 0..31 plus the z column; half 1 covers d 32..63.
__global__ void kScan() {
    __shared__ float s[CS * HTS];         // 4224 B
    __shared__ int   sperm[CS];
    __shared__ float sw[CS];
    int tid = threadIdx.x;                // 128
    int c = blockIdx.x >> 2, table = (blockIdx.x >> 1) & 1, half = blockIdx.x & 1;
    int j0 = c * CS;
    int d0 = half * 32;
    if (tid < CS) {
        sperm[tid] = g_perm[j0 + tid];
        sw[tid] = table ? g_whi[j0 + tid] : g_wlo[j0 + tid];
    }
    __syncthreads();
    int w = tid >> 5, lane = tid & 31;
#pragma unroll
    for (int it = 0; it < 8; it++) {
        int j = it * 4 + w;
        s[j * HTS + lane] = sw[j] * g_h[sperm[j] * D + d0 + lane];
    }
    if (half == 0 && tid < CS) s[tid * HTS + 32] = sw[tid];
    __syncthreads();
    const unsigned F = 0xFFFFFFFFu;
    int ncols = (half == 0) ? 33 : 32;   // col 32 of half 0 = z column
    if (!table) {  // forward inclusive prefix per column (single 32-scan)
        for (int dd = w; dd < ncols; dd += 4) {
            float v = s[lane * HTS + dd];
#pragma unroll
            for (int o = 1; o < 32; o <<= 1) { float t = __shfl_up_sync(F, v, o); if (lane >= o) v += t; }
            s[lane * HTS + dd] = v;
            if (lane == 31) {
                if (dd < 32) g_ofLo[(d0 + dd) * NC + c] = v; else g_ofzLo[c] = v;
            }
        }
    } else {       // backward inclusive suffix per column
        for (int dd = w; dd < ncols; dd += 4) {
            float v = s[lane * HTS + dd];
#pragma unroll
            for (int o = 1; o < 32; o <<= 1) { float t = __shfl_down_sync(F, v, o); if (lane + o < 32) v += t; }
            s[lane * HTS + dd] = v;
            if (lane == 0) {
                if (dd < 32) g_ofHi[(d0 + dd) * NC + c] = v; else g_ofzHi[c] = v;
            }
        }
    }
    __syncthreads();
    if (!table) {
#pragma unroll
        for (int it = 0; it < 8; it++) {
            int j = it * 4 + w;
            g_LoP[(j0 + j + 1) * D + d0 + lane] = s[j * HTS + lane];
        }
        if (half == 0 && tid < CS) g_zLo[j0 + tid + 1] = s[tid * HTS + 32];
        if (c == 0) {
            if (tid < 32) g_LoP[d0 + tid] = 0.f;
            if (half == 0 && tid == 32) g_zLo[0] = 0.f;
        }
    } else {
#pragma unroll
        for (int it = 0; it < 8; it++) {
            int j = it * 4 + w;
            g_HiS[(j0 + j) * D + d0 + lane] = s[j * HTS + lane];
        }
        if (half == 0 && tid < CS) g_zHi[j0 + tid] = s[tid * HTS + 32];
        if (c == NC - 1) {
            if (tid < 32) g_HiS[NN * D + d0 + tid] = 0.f;
            if (half == 0 && tid == 32) g_zHi[NN] = 0.f;
        }
    }
}

// ---------------- kS2: scan 256 chunk totals per column -> exclusive offsets ----------------
__global__ void kS2() {
    int t = blockIdx.x * 4 + (threadIdx.x >> 5);
    int lane = threadIdx.x & 31;
    if (t >= 130) return;
    const unsigned F = 0xFFFFFFFFu;
    float* base;
    bool fwd;
    if (t < 64)        { base = g_ofLo + t * NC;        fwd = true;  }
    else if (t < 128)  { base = g_ofHi + (t - 64) * NC; fwd = false; }
    else if (t == 128) { base = g_ofzLo;                fwd = true;  }
    else               { base = g_ofzHi;                fwd = false; }
    float carry = 0.f;
    if (fwd) {
#pragma unroll
        for (int m = 0; m < 8; m++) {
            float v = base[m * 32 + lane];
            float x = v;
#pragma unroll
            for (int o = 1; o < 32; o <<= 1) { float s = __shfl_up_sync(F, x, o); if (lane >= o) x += s; }
            float incl = x + carry;
            base[m * 32 + lane] = incl - v;        // exclusive prefix
            carry = __shfl_sync(F, incl, 31);
        }
    } else {
#pragma unroll
        for (int m = 7; m >= 0; m--) {
            float v = base[m * 32 + lane];
            float x = v;
#pragma unroll
            for (int o = 1; o < 32; o <<= 1) { float s = __shfl_down_sync(F, x, o); if (lane + o < 32) x += s; }
            float incl = x + carry;
            base[m * 32 + lane] = incl - v;        // exclusive suffix
            carry = __shfl_sync(F, incl, 0);
        }
    }
}

// ---------------- kOut: per-row combine + ELU (smem-staged search) ----------------
__global__ void kOut(float* __restrict__ out) {
    __shared__ float sf[256];             // f2s samples at stride 32
    int tid = threadIdx.x;                // 256
    sf[tid] = g_f2s[tid * 32];
    __syncthreads();
    int w = tid >> 5, lane = tid & 31;
    int i = blockIdx.x * 8 + w;
    float f1 = g_f1[i];
    float thr = -f1;
    const unsigned F = 0xFFFFFFFFu;
    // window: lo = # samples <= thr (all lanes compute identically, LDS broadcast)
    int lo = 0, hi = 256;
#pragma unroll
    for (int it = 0; it < 8; it++) { int m = (lo + hi) >> 1; lo = (sf[m] <= thr) ? m + 1 : lo; hi = (sf[m] <= thr) ? hi : m; }
    int k;
    if (lo == 0) {
        __ballot_sync(F, false);
        k = 0;
    } else {
        int win = lo - 1;                 // f2s[win*32] <= thr; k in [win*32+1, win*32+32]
        int idx = win * 32 + 1 + lane;
        unsigned m = __ballot_sync(F, (idx < NN) ? (g_f2s[idx] <= thr) : false);
        k = win * 32 + 1 + __popc(m);
    }
    int ckLo = (k == 0) ? 0 : ((k - 1) >> 5);
    int ckHi = k >> 5;
    bool hasHi = (k < NN);
    float e1 = expf(f1), ea = expf(ALPHA * f1);
    float zLoV = g_zLo[k] + g_ofzLo[ckLo];
    float zHiV = hasHi ? (g_zHi[k] + g_ofzHi[ckHi]) : 0.f;
    float inv = 1.0f / (e1 * zHiV + ea * zLoV);
#pragma unroll
    for (int p = 0; p < 2; p++) {
        int d = lane + 32 * p;
        float lov = g_LoP[k * D + d] + g_ofLo[d * NC + ckLo];
        float hiv = hasHi ? (g_HiS[k * D + d] + g_ofHi[d * NC + ckHi]) : 0.f;
        float r = (e1 * hiv + ea * lov) * inv;
        out[i * D + d] = (r > 0.f) ? r : (expf(r) - 1.f);
    }
}

extern "C" void kernel_launch(void* const* d_in, const int* in_sizes, int n_in,
                              void* d_out, int out_size) {
    const float* x  = (const float*)d_in[0];
    const float* Wt = (const float*)d_in[1];
    const float* a1 = (const float*)d_in[2];
    const float* b1 = (const float*)d_in[3];
    const float* a2 = (const float*)d_in[4];
    const float* b2 = (const float*)d_in[5];
    float* out = (float*)d_out;

    k1<<<NN / 16, 256>>>(x, Wt, a1, b1, a2, b2);
    kRank<<<1024, 128>>>();
    kScatter<<<32, 256>>>();
    kScan<<<NC * 4, 128>>>();
    kS2<<<33, 128>>>();
    kOut<<<NN / 8, 256>>>(out);
}

// round 7
// speedup vs baseline: 2.7227x; 1.0470x over previous
#include <cuda_runtime.h>

#define NN 8192
#define D 64
#define ALPHA 0.2f
#define CS 32          // scan chunk size (one warp-scan, no carry chain)
#define NC 256         // number of chunks (NN/CS)
#define HTS 33         // half-tile stride: 33 % 32 == 1 -> conflict-free columns

// ---------------- device scratch (no allocation allowed) ----------------
__device__ float g_h[NN * D];
__device__ float g_f1[NN];
__device__ float g_f2[NN];
__device__ unsigned g_key[NN];
__device__ int   g_rank[NN];
__device__ int   g_perm[NN];
__device__ float g_f2s[NN];
__device__ float g_wlo[NN];            // exp(alpha * f2), sorted order
__device__ float g_whi[NN];            // exp(f2), sorted order
__device__ float g_LoP[(NN + 1) * D];  // chunk-local fwd prefix of wlo*h
__device__ float g_HiS[(NN + 1) * D];  // chunk-local bwd suffix of whi*h
__device__ float g_zLo[NN + 1];
__device__ float g_zHi[NN + 1];
__device__ float g_ofLo[D * NC];       // per (d, chunk): totals -> exclusive offsets
__device__ float g_ofHi[D * NC];
__device__ float g_ofzLo[NC];
__device__ float g_ofzHi[NC];

// ---------------- k1: h = x@Wt, f1/f2, 32-bit sort keys, zero ranks ----------------
__global__ void k1(const float* __restrict__ x, const float* __restrict__ Wt,
                   const float* __restrict__ a1, const float* __restrict__ b1,
                   const float* __restrict__ a2, const float* __restrict__ b2) {
    __shared__ float sW[D * D];
    __shared__ float sx[16][D];
    __shared__ float sh[16][D];
    int tid = threadIdx.x;        // 256
    int row0 = blockIdx.x * 16;
    for (int i = tid; i < D * D; i += 256) sW[i] = Wt[i];
    for (int i = tid; i < 16 * D; i += 256) sx[i >> 6][i & 63] = x[row0 * D + i];
    __syncthreads();
    int o = tid & 63, rg = tid >> 6;
    float a0 = 0.f, a1c = 0.f, a2c = 0.f, a3 = 0.f;
#pragma unroll
    for (int i = 0; i < D; i++) {
        float w = sW[i * D + o];
        a0  += sx[rg * 4 + 0][i] * w;
        a1c += sx[rg * 4 + 1][i] * w;
        a2c += sx[rg * 4 + 2][i] * w;
        a3  += sx[rg * 4 + 3][i] * w;
    }
    g_h[(row0 + rg * 4 + 0) * D + o] = a0;
    g_h[(row0 + rg * 4 + 1) * D + o] = a1c;
    g_h[(row0 + rg * 4 + 2) * D + o] = a2c;
    g_h[(row0 + rg * 4 + 3) * D + o] = a3;
    sh[rg * 4 + 0][o] = a0;
    sh[rg * 4 + 1][o] = a1c;
    sh[rg * 4 + 2][o] = a2c;
    sh[rg * 4 + 3][o] = a3;
    __syncthreads();
    int w = tid >> 5, lane = tid & 31;
#pragma unroll
    for (int q = 0; q < 2; q++) {
        int r = w * 2 + q;
        float h0 = sh[r][lane], h1 = sh[r][lane + 32];
        float s1 = h0 * a1[lane] + h1 * a1[lane + 32];
        float s2 = h0 * a2[lane] + h1 * a2[lane + 32];
#pragma unroll
        for (int off = 16; off; off >>= 1) {
            s1 += __shfl_down_sync(0xFFFFFFFFu, s1, off);
            s2 += __shfl_down_sync(0xFFFFFFFFu, s2, off);
        }
        if (lane == 0) {
            int row = row0 + r;
            float f1v = s1 + b1[0], f2v = s2 + b2[0];
            g_f1[row] = f1v;
            g_f2[row] = f2v;
            unsigned u = __float_as_uint(f2v);
            g_key[row] = (u >> 31) ? ~u : (u | 0x80000000u);  // order-preserving
            g_rank[row] = 0;
        }
    }
}

// ---------------- kRank: counting rank sort, 32-bit keys, region tie-break ----------------
// 1024 blocks = eb(64, element-chunk of 128) x cb(16, key-chunk of 512).
// All j in a non-diagonal block are strictly before/after all i of the block.
__global__ void kRank() {
    __shared__ unsigned sk[512];
    int tid = threadIdx.x;  // 128
    int eb = blockIdx.x >> 4, cb = blockIdx.x & 15;
    int i = eb * 128 + tid;
    unsigned ki = g_key[i];
#pragma unroll
    for (int m = 0; m < 4; m++) sk[tid + m * 128] = g_key[cb * 512 + tid + m * 128];
    __syncthreads();
    int cnt = 0;
    int diag = eb >> 2;    // cb containing this eb's i-range
    if (cb == diag) {
        int j0 = cb * 512;
        for (int j = 0; j < 512; j++) {
            unsigned kj = sk[j];
            cnt += (kj < ki) || (kj == ki && (j0 + j) < i);
        }
    } else if (cb < diag) {   // all j < i: ties count
#pragma unroll 8
        for (int j = 0; j < 512; j++) cnt += (sk[j] <= ki);
    } else {                  // all j > i: ties don't count
#pragma unroll 8
        for (int j = 0; j < 512; j++) cnt += (sk[j] < ki);
    }
    atomicAdd(&g_rank[i], cnt);
}

// ---------------- kScatter: into sorted order + exp weights ----------------
__global__ void kScatter() {
    int i = blockIdx.x * 256 + threadIdx.x;
    int r = g_rank[i];
    float f = g_f2[i];
    g_perm[r] = i;
    g_f2s[r] = f;
    g_wlo[r] = expf(ALPHA * f);
    g_whi[r] = expf(f);
}

// ---------------- kScan: 512 blocks (chunk x d-half), BOTH tables per block ----------------
// One gather of the h half-rows feeds both the Lo (fwd) and Hi (bwd) scans.
// half 0 additionally carries the z column (col 32).
__global__ void kScan() {
    __shared__ float sLo[CS * HTS];       // 4224 B
    __shared__ float sHi[CS * HTS];       // 4224 B
    __shared__ int   sperm[CS];
    __shared__ float swlo[CS], swhi[CS];
    int tid = threadIdx.x;                // 256 (8 warps)
    int c = blockIdx.x >> 1, half = blockIdx.x & 1;
    int j0 = c * CS;
    int d0 = half * 32;
    if (tid < CS) {
        sperm[tid] = g_perm[j0 + tid];
        swlo[tid] = g_wlo[j0 + tid];
        swhi[tid] = g_whi[j0 + tid];
    }
    __syncthreads();
    int w = tid >> 5, lane = tid & 31;
#pragma unroll
    for (int it = 0; it < 4; it++) {
        int j = it * 8 + w;
        float hv = g_h[sperm[j] * D + d0 + lane];
        sLo[j * HTS + lane] = swlo[j] * hv;
        sHi[j * HTS + lane] = swhi[j] * hv;
    }
    if (half == 0 && tid < CS) {
        sLo[tid * HTS + 32] = swlo[tid];
        sHi[tid * HTS + 32] = swhi[tid];
    }
    __syncthreads();
    const unsigned F = 0xFFFFFFFFu;
    int ncols = (half == 0) ? 33 : 32;   // col 32 of half 0 = z column
    // warps 0-3: Lo forward scans; warps 4-7: Hi backward scans
    if (w < 4) {
        for (int dd = w; dd < ncols; dd += 4) {
            float v = sLo[lane * HTS + dd];
#pragma unroll
            for (int o = 1; o < 32; o <<= 1) { float t = __shfl_up_sync(F, v, o); if (lane >= o) v += t; }
            sLo[lane * HTS + dd] = v;
            if (lane == 31) {
                if (dd < 32) g_ofLo[(d0 + dd) * NC + c] = v; else g_ofzLo[c] = v;
            }
        }
    } else {
        for (int dd = w - 4; dd < ncols; dd += 4) {
            float v = sHi[lane * HTS + dd];
#pragma unroll
            for (int o = 1; o < 32; o <<= 1) { float t = __shfl_down_sync(F, v, o); if (lane + o < 32) v += t; }
            sHi[lane * HTS + dd] = v;
            if (lane == 0) {
                if (dd < 32) g_ofHi[(d0 + dd) * NC + c] = v; else g_ofzHi[c] = v;
            }
        }
    }
    __syncthreads();
#pragma unroll
    for (int it = 0; it < 4; it++) {
        int j = it * 8 + w;
        g_LoP[(j0 + j + 1) * D + d0 + lane] = sLo[j * HTS + lane];
        g_HiS[(j0 + j) * D + d0 + lane]     = sHi[j * HTS + lane];
    }
    if (half == 0 && tid < CS) {
        g_zLo[j0 + tid + 1] = sLo[tid * HTS + 32];
        g_zHi[j0 + tid]     = sHi[tid * HTS + 32];
    }
    if (c == 0) {
        if (tid < 32) g_LoP[d0 + tid] = 0.f;
        if (half == 0 && tid == 32) g_zLo[0] = 0.f;
    }
    if (c == NC - 1) {
        if (tid < 32) g_HiS[NN * D + d0 + tid] = 0.f;
        if (half == 0 && tid == 32) g_zHi[NN] = 0.f;
    }
}

// ---------------- kS2: scan 256 chunk totals per column -> exclusive offsets ----------------
__global__ void kS2() {
    int t = blockIdx.x * 4 + (threadIdx.x >> 5);
    int lane = threadIdx.x & 31;
    if (t >= 130) return;
    const unsigned F = 0xFFFFFFFFu;
    float* base;
    bool fwd;
    if (t < 64)        { base = g_ofLo + t * NC;        fwd = true;  }
    else if (t < 128)  { base = g_ofHi + (t - 64) * NC; fwd = false; }
    else if (t == 128) { base = g_ofzLo;                fwd = true;  }
    else               { base = g_ofzHi;                fwd = false; }
    float carry = 0.f;
    if (fwd) {
#pragma unroll
        for (int m = 0; m < 8; m++) {
            float v = base[m * 32 + lane];
            float x = v;
#pragma unroll
            for (int o = 1; o < 32; o <<= 1) { float s = __shfl_up_sync(F, x, o); if (lane >= o) x += s; }
            float incl = x + carry;
            base[m * 32 + lane] = incl - v;        // exclusive prefix
            carry = __shfl_sync(F, incl, 31);
        }
    } else {
#pragma unroll
        for (int m = 7; m >= 0; m--) {
            float v = base[m * 32 + lane];
            float x = v;
#pragma unroll
            for (int o = 1; o < 32; o <<= 1) { float s = __shfl_down_sync(F, x, o); if (lane + o < 32) x += s; }
            float incl = x + carry;
            base[m * 32 + lane] = incl - v;        // exclusive suffix
            carry = __shfl_sync(F, incl, 0);
        }
    }
}

// ---------------- kOut: per-row combine + ELU (smem-staged search) ----------------
__global__ void kOut(float* __restrict__ out) {
    __shared__ float sf[256];             // f2s samples at stride 32
    int tid = threadIdx.x;                // 256
    sf[tid] = g_f2s[tid * 32];
    __syncthreads();
    int w = tid >> 5, lane = tid & 31;
    int i = blockIdx.x * 8 + w;
    float f1 = g_f1[i];
    float thr = -f1;
    const unsigned F = 0xFFFFFFFFu;
    int lo = 0, hi = 256;
#pragma unroll
    for (int it = 0; it < 8; it++) { int m = (lo + hi) >> 1; lo = (sf[m] <= thr) ? m + 1 : lo; hi = (sf[m] <= thr) ? hi : m; }
    int k;
    if (lo == 0) {
        __ballot_sync(F, false);
        k = 0;
    } else {
        int win = lo - 1;                 // f2s[win*32] <= thr; k in [win*32+1, win*32+32]
        int idx = win * 32 + 1 + lane;
        unsigned m = __ballot_sync(F, (idx < NN) ? (g_f2s[idx] <= thr) : false);
        k = win * 32 + 1 + __popc(m);
    }
    int ckLo = (k == 0) ? 0 : ((k - 1) >> 5);
    int ckHi = k >> 5;
    bool hasHi = (k < NN);
    float e1 = expf(f1), ea = expf(ALPHA * f1);
    float zLoV = g_zLo[k] + g_ofzLo[ckLo];
    float zHiV = hasHi ? (g_zHi[k] + g_ofzHi[ckHi]) : 0.f;
    float inv = 1.0f / (e1 * zHiV + ea * zLoV);
#pragma unroll
    for (int p = 0; p < 2; p++) {
        int d = lane + 32 * p;
        float lov = g_LoP[k * D + d] + g_ofLo[d * NC + ckLo];
        float hiv = hasHi ? (g_HiS[k * D + d] + g_ofHi[d * NC + ckHi]) : 0.f;
        float r = (e1 * hiv + ea * lov) * inv;
        out[i * D + d] = (r > 0.f) ? r : (expf(r) - 1.f);
    }
}

extern "C" void kernel_launch(void* const* d_in, const int* in_sizes, int n_in,
                              void* d_out, int out_size) {
    const float* x  = (const float*)d_in[0];
    const float* Wt = (const float*)d_in[1];
    const float* a1 = (const float*)d_in[2];
    const float* b1 = (const float*)d_in[3];
    const float* a2 = (const float*)d_in[4];
    const float* b2 = (const float*)d_in[5];
    float* out = (float*)d_out;

    k1<<<NN / 16, 256>>>(x, Wt, a1, b1, a2, b2);
    kRank<<<1024, 128>>>();
    kScatter<<<32, 256>>>();
    kScan<<<NC * 2, 256>>>();
    kS2<<<33, 128>>>();
    kOut<<<NN / 8, 256>>>(out);
}